// round 1
// baseline (speedup 1.0000x reference)
#include <cuda_runtime.h>

// Problem constants
#define G_     2
#define BATCH_ 128
#define L_     2048
#define SD_    64
#define ID_    16
#define OD_    16

// ---------- f32x2 packed helpers ----------
__device__ __forceinline__ unsigned long long pack2(float lo, float hi) {
    unsigned long long r;
    asm("mov.b64 %0, {%1, %2};" : "=l"(r) : "f"(lo), "f"(hi));
    return r;
}
__device__ __forceinline__ void unpack2(unsigned long long v, float& lo, float& hi) {
    asm("mov.b64 {%0, %1}, %2;" : "=f"(lo), "=f"(hi) : "l"(v));
}
__device__ __forceinline__ void fma2(unsigned long long& acc, unsigned long long a, unsigned long long b) {
    asm("fma.rn.f32x2 %0, %1, %2, %0;" : "+l"(acc) : "l"(a), "l"(b));
}

// One block per (g,b) sequence; 64 threads, thread t owns state dim t.
__global__ void __launch_bounds__(64)
lsg_scan_kernel(const float* __restrict__ state,
                const float* __restrict__ inputs,
                const float* __restrict__ Fm,
                const float* __restrict__ Bm,
                const float* __restrict__ Hm,
                const float* __restrict__ SW,
                const float* __restrict__ SV,
                const float* __restrict__ wn,
                const float* __restrict__ vnz,
                float* __restrict__ states_out,
                float* __restrict__ obs_out)
{
    const int t  = threadIdx.x;           // 0..63
    const int gb = blockIdx.x;            // 0..255
    const int g  = gb / BATCH_;
    const int b  = gb % BATCH_;

    __shared__ __align__(16) float s_sh[2][SD_];     // state double buffer
    __shared__ __align__(16) float w_sh[2][SD_];     // staged colored-noise input (raw w)
    __shared__ __align__(16) float in_sh[2][ID_];    // staged inputs
    __shared__ __align__(16) float vn_sh[2][OD_];    // staged v noise
    __shared__ __align__(16) float part_sh[2][SD_];  // H-partials double buffer

    // ---- per-thread matrix rows in registers (f32x2 packed) ----
    unsigned long long f2v[SD_/2], sw2[SD_/2], b2v[ID_/2], h2v[8], sv2[OD_/2];
    {
        const float* Frow  = Fm + ((size_t)g*SD_ + t)*SD_;
        const float* SWrow = SW + ((size_t)g*SD_ + t)*SD_;
        #pragma unroll
        for (int i = 0; i < SD_/2; i++) {
            f2v[i] = pack2(Frow[2*i],  Frow[2*i+1]);
            sw2[i] = pack2(SWrow[2*i], SWrow[2*i+1]);
        }
        const float* Brow = Bm + ((size_t)g*SD_ + t)*ID_;
        #pragma unroll
        for (int i = 0; i < ID_/2; i++) b2v[i] = pack2(Brow[2*i], Brow[2*i+1]);

        const int p = t & 15, q = t >> 4;
        const float* Hrow = Hm + ((size_t)g*OD_ + p)*SD_ + q*16;
        #pragma unroll
        for (int i = 0; i < 8; i++) h2v[i] = pack2(Hrow[2*i], Hrow[2*i+1]);

        if (t < OD_) {
            const float* SVrow = SV + ((size_t)g*OD_ + t)*OD_;
            #pragma unroll
            for (int i = 0; i < OD_/2; i++) sv2[i] = pack2(SVrow[2*i], SVrow[2*i+1]);
        }
    }

    // initial state
    s_sh[0][t] = state[(size_t)gb*SD_ + t];

    const float* w_base  = wn  + ((size_t)g*BATCH_ + b)*SD_;   // + l * G*B*SD
    const float* in_base = inputs + (size_t)gb*L_*ID_;          // + l * ID
    const float* vn_base = vnz + ((size_t)g*BATCH_ + b)*OD_;   // + l * G*B*OD
    const long wstep = (long)G_*BATCH_*SD_;
    const long vstep = (long)G_*BATCH_*OD_;

    // prefetch ring, depth 4 (hides ~577cyc DRAM latency behind ~4 steps)
    float w_pf[4], in_pf[4], vn_pf[4];
    #pragma unroll
    for (int j = 0; j < 4; j++) {
        w_pf[j] = w_base[(long)j*wstep + t];
        if (t < ID_) in_pf[j] = in_base[(long)j*ID_ + t];
        if (t < OD_) vn_pf[j] = vn_base[(long)j*vstep + t];
    }

    float* st_out = states_out + (size_t)gb*L_*SD_;
    float* ob_out = obs_out    + (size_t)gb*L_*OD_;

    for (int l4 = 0; l4 < L_; l4 += 4) {
        #pragma unroll
        for (int j = 0; j < 4; j++) {
            const int l  = l4 + j;
            const int pb = l & 1;

            // ---- stage this step's global data into shared ----
            w_sh[pb][t] = w_pf[j];
            if (t < ID_) in_sh[pb][t] = in_pf[j];
            if (t < OD_) vn_sh[pb][t] = vn_pf[j];

            // ---- prefetch step l+4 ----
            const int lp = l + 4;
            if (lp < L_) {
                w_pf[j] = w_base[(long)lp*wstep + t];
                if (t < ID_) in_pf[j] = in_base[(long)lp*ID_ + t];
                if (t < OD_) vn_pf[j] = vn_base[(long)lp*vstep + t];
            }

            __syncthreads();   // B1: staged data + part_sh[pb^1] + s_sh[pb] visible

            // ---- finalize observation for step l-1 (deferred; overlaps this step) ----
            if (l > 0 && t < OD_) {
                const int fb = pb ^ 1;
                float o = (part_sh[fb][t]    + part_sh[fb][t+16])
                        + (part_sh[fb][t+32] + part_sh[fb][t+48]);
                unsigned long long oacc = 0ULL;
                const unsigned long long* vnp = (const unsigned long long*)vn_sh[fb];
                #pragma unroll
                for (int i = 0; i < OD_/2; i++) fma2(oacc, sv2[i], vnp[i]);
                float a0, a1; unpack2(oacc, a0, a1);
                ob_out[(long)(l-1)*OD_ + t] = o + a0 + a1;
            }

            // ---- s_l[t] = F[t,:]·s_{l-1} + SW[t,:]·w_l + B[t,:]·u_l ----
            unsigned long long acc0 = 0ULL, acc1 = 0ULL, acc2 = 0ULL, acc3 = 0ULL;
            const unsigned long long* sp = (const unsigned long long*)s_sh[pb];
            const unsigned long long* wp = (const unsigned long long*)w_sh[pb];
            const unsigned long long* ip = (const unsigned long long*)in_sh[pb];
            #pragma unroll
            for (int i = 0; i < SD_/2; i += 4) {
                fma2(acc0, f2v[i],   sp[i]);
                fma2(acc1, f2v[i+1], sp[i+1]);
                fma2(acc2, f2v[i+2], sp[i+2]);
                fma2(acc3, f2v[i+3], sp[i+3]);
            }
            #pragma unroll
            for (int i = 0; i < SD_/2; i += 4) {
                fma2(acc0, sw2[i],   wp[i]);
                fma2(acc1, sw2[i+1], wp[i+1]);
                fma2(acc2, sw2[i+2], wp[i+2]);
                fma2(acc3, sw2[i+3], wp[i+3]);
            }
            #pragma unroll
            for (int i = 0; i < ID_/2; i += 4) {
                fma2(acc0, b2v[i],   ip[i]);
                fma2(acc1, b2v[i+1], ip[i+1]);
                fma2(acc2, b2v[i+2], ip[i+2]);
                fma2(acc3, b2v[i+3], ip[i+3]);
            }
            float x0,x1,y0,y1,z0,z1,u0,u1;
            unpack2(acc0,x0,x1); unpack2(acc1,y0,y1);
            unpack2(acc2,z0,z1); unpack2(acc3,u0,u1);
            const float sval = ((x0+x1)+(y0+y1)) + ((z0+z1)+(u0+u1));

            s_sh[pb^1][t] = sval;
            st_out[(long)l*SD_ + t] = sval;

            __syncthreads();   // B2: s_l complete in shared

            // ---- H partial: thread (q,p) covers s range [q*16, q*16+16) ----
            {
                const int q = t >> 4;
                unsigned long long pacc = 0ULL;
                const unsigned long long* snp =
                    (const unsigned long long*)(s_sh[pb^1] + q*16);
                #pragma unroll
                for (int i = 0; i < 8; i++) fma2(pacc, h2v[i], snp[i]);
                float a0, a1; unpack2(pacc, a0, a1);
                part_sh[pb][t] = a0 + a1;
            }
        }
    }

    // ---- epilogue: observation for l = L-1 ----
    __syncthreads();
    if (t < OD_) {
        const int fb = (L_ - 1) & 1;
        float o = (part_sh[fb][t]    + part_sh[fb][t+16])
                + (part_sh[fb][t+32] + part_sh[fb][t+48]);
        unsigned long long oacc = 0ULL;
        const unsigned long long* vnp = (const unsigned long long*)vn_sh[fb];
        #pragma unroll
        for (int i = 0; i < OD_/2; i++) fma2(oacc, sv2[i], vnp[i]);
        float a0, a1; unpack2(oacc, a0, a1);
        ob_out[(long)(L_-1)*OD_ + t] = o + a0 + a1;
    }
}

extern "C" void kernel_launch(void* const* d_in, const int* in_sizes, int n_in,
                              void* d_out, int out_size) {
    const float* state  = (const float*)d_in[0];   // [G,B,S]
    const float* inputs = (const float*)d_in[1];   // [G,B,L,I]
    const float* Fm     = (const float*)d_in[2];   // [G,S,S]
    const float* Bm     = (const float*)d_in[3];   // [G,S,I]
    const float* Hm     = (const float*)d_in[4];   // [G,O,S]
    const float* SW     = (const float*)d_in[5];   // [G,S,S]
    const float* SV     = (const float*)d_in[6];   // [G,O,O]
    const float* wn     = (const float*)d_in[7];   // [L,G,B,S]
    const float* vn     = (const float*)d_in[8];   // [L,G,B,O]

    float* states_out = (float*)d_out;                                   // [G,B,L,S]
    float* obs_out    = states_out + (size_t)G_*BATCH_*L_*SD_;           // [G,B,L,O]

    lsg_scan_kernel<<<G_*BATCH_, 64>>>(state, inputs, Fm, Bm, Hm, SW, SV,
                                       wn, vn, states_out, obs_out);
}